// round 12
// baseline (speedup 1.0000x reference)
#include <cuda_runtime.h>
#include <cuda_bf16.h>
#include <cstdint>
#include <math.h>

#define N_SPK 512
#define N_UTT 64
#define D     1024
#define NM    (N_SPK * N_UTT)   // 32768
#define EPS   1e-6f
#define FP8_SCALE 16.0f          // embeddings scaled by 16 -> dot = 256*cos
#define INV_DOT_SCALE 0.00390625f // 1/256

// ---------------- scratch (device globals; no runtime allocation) ----------
__device__ uint8_t        g_cnorm[N_SPK * D];        // e4m3 centroids *16 (512 KiB)
__device__ uint8_t        g_enorm[(size_t)NM * D];   // e4m3 utterances *16 (32 MiB)
__device__ float          g_cos_self[NM];
__device__ float          g_prow[(size_t)NM * 4];    // per-row partial sum(exp) per N-slab
__device__ float          g_partial[128];
__device__ unsigned int   g_ctr = 0;                 // monotonic; %128 used per launch

// ---------------- helpers ---------------------------------------------------
__device__ __forceinline__ uint32_t smem_u32(const void* p) {
    uint32_t a;
    asm("{ .reg .u64 t; cvta.to.shared.u64 t, %1; cvt.u32.u64 %0, t; }" : "=r"(a) : "l"(p));
    return a;
}
__device__ __forceinline__ void cp_async16(uint32_t saddr, const void* gsrc) {
    asm volatile("cp.async.cg.shared.global [%0], [%1], 16;" :: "r"(saddr), "l"(gsrc) : "memory");
}
__device__ __forceinline__ void cp_commit() {
    asm volatile("cp.async.commit_group;" ::: "memory");
}
template <int N>
__device__ __forceinline__ void cp_wait() {
    asm volatile("cp.async.wait_group %0;" :: "n"(N) : "memory");
}
__device__ __forceinline__ void ldsm_x4(uint32_t& r0, uint32_t& r1, uint32_t& r2, uint32_t& r3,
                                        uint32_t addr) {
    asm volatile("ldmatrix.sync.aligned.m8n8.x4.shared.b16 {%0,%1,%2,%3}, [%4];"
                 : "=r"(r0), "=r"(r1), "=r"(r2), "=r"(r3) : "r"(addr));
}
// pack 4 floats -> 4 e4m3 bytes (little-endian order a,b,c,d)
__device__ __forceinline__ uint32_t pack_e4m3_4(float a, float b, float c, float d) {
    uint16_t lo, hi;
    asm("cvt.rn.satfinite.e4m3x2.f32 %0, %1, %2;" : "=h"(lo) : "f"(b), "f"(a));
    asm("cvt.rn.satfinite.e4m3x2.f32 %0, %1, %2;" : "=h"(hi) : "f"(d), "f"(c));
    return (uint32_t)lo | ((uint32_t)hi << 16);
}

__device__ __forceinline__ float warpReduceSum(float v) {
    #pragma unroll
    for (int o = 16; o > 0; o >>= 1) v += __shfl_xor_sync(0xFFFFFFFFu, v, o);
    return v;
}
__device__ __forceinline__ float blockReduceSumBcast(float v, float* sred) {
    int lane = threadIdx.x & 31, w = threadIdx.x >> 5;
    int nw = blockDim.x >> 5;
    v = warpReduceSum(v);
    if (lane == 0) sred[w] = v;
    __syncthreads();
    if (threadIdx.x < 32) {
        float x = (threadIdx.x < nw) ? sred[threadIdx.x] : 0.0f;
        x = warpReduceSum(x);
        if (threadIdx.x == 0) sred[0] = x;
    }
    __syncthreads();
    float r = sred[0];
    __syncthreads();
    return r;
}

// ---------------- kernel 1: single-DRAM-pass pre ----------------------------
// One CTA per speaker, 256 threads, 128 KiB dynamic smem holds the speaker's
// 64x1024 block as bf16. Pass 1: DRAM read + smem buffer + speaker sum.
// Pass 2: warp-parallel per-utterance stats from SMEM (no DRAM re-read).
#define PRE_SMEM (N_UTT * D * 2)   // 131072
__global__ void __launch_bounds__(256) pre_kernel(const float* __restrict__ inp) {
    extern __shared__ __align__(16) char dsm[];     // bf16 X[64][1024]
    __shared__ float Ssh[D];                        // speaker sum vector (4 KiB)
    __shared__ float sred[32];
    const int n = blockIdx.x, t = threadIdx.x;
    const int lane = t & 31, w = t >> 5;
    const float4* base = reinterpret_cast<const float4*>(inp) + (size_t)n * N_UTT * (D / 4) + t;
    __nv_bfloat162* Xb = reinterpret_cast<__nv_bfloat162*>(dsm);

    // ---- pass 1: read once, buffer bf16, accumulate speaker sum ----
    float4 s = make_float4(0.f, 0.f, 0.f, 0.f);
    #pragma unroll 8
    for (int m = 0; m < N_UTT; ++m) {
        float4 v = base[(size_t)m * (D / 4)];
        s.x += v.x; s.y += v.y; s.z += v.z; s.w += v.w;
        Xb[m * (D / 2) + 2 * t]     = __floats2bfloat162_rn(v.x, v.y);
        Xb[m * (D / 2) + 2 * t + 1] = __floats2bfloat162_rn(v.z, v.w);
    }
    reinterpret_cast<float4*>(Ssh)[t] = s;
    const float invM = 1.0f / (float)N_UTT;
    float4 c = make_float4(s.x * invM, s.y * invM, s.z * invM, s.w * invM);
    float ss = c.x * c.x + c.y * c.y + c.z * c.z + c.w * c.w;
    ss = blockReduceSumBcast(ss, sred);   // barrier also publishes Xb + Ssh
    {
        float inv = FP8_SCALE / sqrtf(fmaxf(ss, EPS));
        reinterpret_cast<uint32_t*>(g_cnorm)[(size_t)n * (D / 4) + t] =
            pack_e4m3_4(c.x * inv, c.y * inv, c.z * inv, c.w * inv);
    }

    // ---- pass 2: warp-parallel utterances from SMEM ----
    const float invE = 1.0f / (float)(N_UTT - 1);
    const float4* Sv = reinterpret_cast<const float4*>(Ssh);
    for (int m = w; m < N_UTT; m += 8) {
        const uint4* xrow = reinterpret_cast<const uint4*>(dsm + m * (D * 2));  // 128 x 16B
        float xx = 0.f, uu = 0.f, xu = 0.f;
        #pragma unroll
        for (int j = 0; j < 4; ++j) {
            const int idx = lane + 32 * j;           // uint4 index, covers cols 8*idx..8*idx+7
            uint4 p = xrow[idx];
            float2 x01 = __bfloat1622float2(*reinterpret_cast<__nv_bfloat162*>(&p.x));
            float2 x23 = __bfloat1622float2(*reinterpret_cast<__nv_bfloat162*>(&p.y));
            float2 x45 = __bfloat1622float2(*reinterpret_cast<__nv_bfloat162*>(&p.z));
            float2 x67 = __bfloat1622float2(*reinterpret_cast<__nv_bfloat162*>(&p.w));
            float4 S0 = Sv[idx * 2], S1 = Sv[idx * 2 + 1];
            float u0 = (S0.x - x01.x) * invE, u1 = (S0.y - x01.y) * invE;
            float u2 = (S0.z - x23.x) * invE, u3 = (S0.w - x23.y) * invE;
            float u4 = (S1.x - x45.x) * invE, u5 = (S1.y - x45.y) * invE;
            float u6 = (S1.z - x67.x) * invE, u7 = (S1.w - x67.y) * invE;
            xx += x01.x*x01.x + x01.y*x01.y + x23.x*x23.x + x23.y*x23.y
                + x45.x*x45.x + x45.y*x45.y + x67.x*x67.x + x67.y*x67.y;
            uu += u0*u0 + u1*u1 + u2*u2 + u3*u3 + u4*u4 + u5*u5 + u6*u6 + u7*u7;
            xu += x01.x*u0 + x01.y*u1 + x23.x*u2 + x23.y*u3
                + x45.x*u4 + x45.y*u5 + x67.x*u6 + x67.y*u7;
        }
        xx = warpReduceSum(xx);
        uu = warpReduceSum(uu);
        xu = warpReduceSum(xu);
        const float invx = 1.0f / sqrtf(fmaxf(xx, EPS));
        const float invu = 1.0f / sqrtf(fmaxf(uu, EPS));
        if (lane == 0) g_cos_self[n * N_UTT + m] = xu * invx * invu;
        const float sc = invx * FP8_SCALE;
        uint2* erow = reinterpret_cast<uint2*>(g_enorm + (size_t)(n * N_UTT + m) * D);
        #pragma unroll
        for (int j = 0; j < 4; ++j) {
            const int idx = lane + 32 * j;
            uint4 p = xrow[idx];
            float2 x01 = __bfloat1622float2(*reinterpret_cast<__nv_bfloat162*>(&p.x));
            float2 x23 = __bfloat1622float2(*reinterpret_cast<__nv_bfloat162*>(&p.y));
            float2 x45 = __bfloat1622float2(*reinterpret_cast<__nv_bfloat162*>(&p.z));
            float2 x67 = __bfloat1622float2(*reinterpret_cast<__nv_bfloat162*>(&p.w));
            uint2 pk;
            pk.x = pack_e4m3_4(x01.x * sc, x01.y * sc, x23.x * sc, x23.y * sc);
            pk.y = pack_e4m3_4(x45.x * sc, x45.y * sc, x67.x * sc, x67.y * sc);
            erow[idx] = pk;
        }
    }
}

// ---------------- kernel 2: fused FP8 GEMM + sum(exp) epilogue -------------
// Block tile 128x128, BK=64 e4m3 (64B rows), 3-stage cp.async, ldmatrix,
// mma.m16n8k32.e4m3, 2 CTAs/SM, single barrier per iteration.
#define TILE_B   8192                       // 128 rows x 64 bytes
#define STAGE_B  (2 * TILE_B)               // A + B = 16 KiB
__device__ __forceinline__ uint32_t swz(int row, int chunk) {
    return (uint32_t)(row * 64 + ((chunk ^ ((row >> 1) & 3)) << 4));
}

__global__ void __launch_bounds__(256, 2) gemm_fused(const float* __restrict__ wp,
                                                     const float* __restrict__ bp) {
    __shared__ __align__(16) char smem_raw[3 * STAGE_B];   // 48 KiB
    float* sred = reinterpret_cast<float*>(smem_raw);      // aliased in epilogue

    const int tid = threadIdx.x;
    const int bm = blockIdx.x, bn = blockIdx.y;
    const int warp = tid >> 5, lane = tid & 31;
    const int wm = warp & 1, wn = warp >> 1;     // 2 x 4 warp grid, warp tile 64x32
    const int g = lane >> 2, tg = lane & 3;
    const float W = *wp, Bb = *bp;
    const float Ws = W * INV_DOT_SCALE;          // acc = 256*cos
    const uint32_t sb = smem_u32(smem_raw);

    float acc[4][4][4];
    #pragma unroll
    for (int a = 0; a < 4; ++a)
        #pragma unroll
        for (int b = 0; b < 4; ++b)
            #pragma unroll
            for (int c = 0; c < 4; ++c) acc[a][b][c] = 0.f;

    const int r0 = tid >> 2, ch0 = tid & 3;
    const uint8_t* Ag = g_enorm + (size_t)(bm * 128 + r0) * D + ch0 * 16;
    const uint8_t* Bg = g_cnorm + (size_t)(bn * 128 + r0) * D + ch0 * 16;
    const uint32_t sa_lo = swz(r0, ch0), sa_hi = swz(r0 + 64, ch0);

    auto load_stage = [&](int stage, int kb) {
        const uint32_t base = sb + stage * STAGE_B;
        cp_async16(base + sa_lo,          Ag + kb);
        cp_async16(base + sa_hi,          Ag + (size_t)64 * D + kb);
        cp_async16(base + TILE_B + sa_lo, Bg + kb);
        cp_async16(base + TILE_B + sa_hi, Bg + (size_t)64 * D + kb);
    };

    const int a_row = wm * 64 + (lane & 15);                      // + mi*16
    const int a_ch  = lane >> 4;                                  // + kc
    const int b_row = wn * 32 + (lane & 7) + ((lane >> 4) << 3);  // + np*16
    const int b_ch  = (lane >> 3) & 1;                            // + kc

    // prologue
    load_stage(0, 0);  cp_commit();
    load_stage(1, 64); cp_commit();
    cp_wait<1>();
    __syncthreads();

    const int NKT = D / 64;  // 16
    for (int kt = 0; kt < NKT; ++kt) {
        const uint32_t abase = sb + (kt % 3) * STAGE_B;
        const uint32_t bbase = abase + TILE_B;
        #pragma unroll
        for (int kk = 0; kk < 2; ++kk) {       // two k32 halves of BK=64
            const int kc = kk * 2;             // 16B chunk index: 0 or 2
            uint32_t af[4][4];
            #pragma unroll
            for (int mi = 0; mi < 4; ++mi)
                ldsm_x4(af[mi][0], af[mi][1], af[mi][2], af[mi][3],
                        abase + swz(a_row + mi * 16, kc + a_ch));
            uint32_t bf_[4][2];
            #pragma unroll
            for (int np = 0; np < 2; ++np)
                ldsm_x4(bf_[2 * np][0], bf_[2 * np][1], bf_[2 * np + 1][0], bf_[2 * np + 1][1],
                        bbase + swz(b_row + np * 16, kc + b_ch));
            #pragma unroll
            for (int mi = 0; mi < 4; ++mi)
                #pragma unroll
                for (int ni = 0; ni < 4; ++ni) {
                    asm volatile(
                        "mma.sync.aligned.m16n8k32.row.col.f32.e4m3.e4m3.f32 "
                        "{%0,%1,%2,%3}, {%4,%5,%6,%7}, {%8,%9}, {%0,%1,%2,%3};\n"
                        : "+f"(acc[mi][ni][0]), "+f"(acc[mi][ni][1]),
                          "+f"(acc[mi][ni][2]), "+f"(acc[mi][ni][3])
                        : "r"(af[mi][0]), "r"(af[mi][1]), "r"(af[mi][2]), "r"(af[mi][3]),
                          "r"(bf_[ni][0]), "r"(bf_[ni][1]));
                }
        }
        if (kt + 2 < NKT) load_stage((kt + 2) % 3, (kt + 2) * 64);
        cp_commit();          // empty group when no loads -> uniform wait depth
        cp_wait<1>();         // stage kt+1 resident
        __syncthreads();      // one barrier per iteration
    }

    // ---- epilogue: per-row sum(exp(Ws*acc + B)), diag column excluded ----
    const int dcol_local = 2 * bm + wm - bn * 128;
    #pragma unroll
    for (int mi = 0; mi < 4; ++mi) {
        #pragma unroll
        for (int half = 0; half < 2; ++half) {
            float ex = 0.0f;
            #pragma unroll
            for (int ni = 0; ni < 4; ++ni) {
                const int c0 = wn * 32 + ni * 8 + 2 * tg;
                const float v0 = acc[mi][ni][half * 2 + 0];
                const float v1 = acc[mi][ni][half * 2 + 1];
                ex += (c0     == dcol_local) ? 0.0f : __expf(fmaf(Ws, v0, Bb));
                ex += (c0 + 1 == dcol_local) ? 0.0f : __expf(fmaf(Ws, v1, Bb));
            }
            ex += __shfl_xor_sync(0xFFFFFFFFu, ex, 1);
            ex += __shfl_xor_sync(0xFFFFFFFFu, ex, 2);
            if (tg == 0) {
                const int row_local = wm * 64 + mi * 16 + half * 8 + g;
                sred[row_local * 4 + wn] = ex;
            }
        }
    }
    __syncthreads();
    if (tid < 128) {
        const float* p = sred + tid * 4;
        const float S = (p[0] + p[1]) + (p[2] + p[3]);
        g_prow[(size_t)(bm * 128 + tid) * 4 + bn] = S;
    }
}

// ---------------- kernel 3: merge + threadfence final reduction ------------
// 128 blocks x 256 threads. Last-arriving block (atomic counter, replay-safe
// via %128) re-reduces the 128 partials in fixed order -> deterministic.
__global__ void __launch_bounds__(256) merge_kernel(const float* __restrict__ wp,
                                                    const float* __restrict__ bp,
                                                    float* __restrict__ out) {
    __shared__ float sred[32];
    __shared__ int slast;
    const int i = blockIdx.x * 256 + threadIdx.x;
    const float W = *wp, Bb = *bp;
    const float cs = g_cos_self[i];
    const float pos = fmaf(W, cs, Bb);
    const float4 p = *reinterpret_cast<const float4*>(g_prow + (size_t)i * 4);
    const float S = ((p.x + p.y) + (p.z + p.w)) + __expf(pos);
    float loss = __logf(S) - pos;
    loss = blockReduceSumBcast(loss, sred);
    if (threadIdx.x == 0) {
        g_partial[blockIdx.x] = loss;
        __threadfence();
        unsigned int old = atomicAdd(&g_ctr, 1u);
        slast = ((old & 127u) == 127u) ? 1 : 0;
    }
    __syncthreads();
    if (slast) {
        float v = (threadIdx.x < 128) ? g_partial[threadIdx.x] : 0.0f;
        v = blockReduceSumBcast(v, sred);
        if (threadIdx.x == 0) out[0] = v;
    }
}

// ---------------- launch ----------------------------------------------------
extern "C" void kernel_launch(void* const* d_in, const int* in_sizes, int n_in,
                              void* d_out, int out_size) {
    const float* inp = (const float*)d_in[0];
    const float* w   = (const float*)d_in[1];
    const float* b   = (const float*)d_in[2];
    float* out = (float*)d_out;

    cudaFuncSetAttribute(pre_kernel, cudaFuncAttributeMaxDynamicSharedMemorySize, PRE_SMEM);

    pre_kernel<<<N_SPK, 256, PRE_SMEM>>>(inp);
    dim3 gg(NM / 128, N_SPK / 128);
    gemm_fused<<<gg, 256>>>(w, b);
    merge_kernel<<<NM / 256, 256>>>(w, b, out);
}

// round 13
// speedup vs baseline: 1.1154x; 1.1154x over previous
#include <cuda_runtime.h>
#include <cuda_bf16.h>
#include <cstdint>
#include <math.h>

#define N_SPK 512
#define N_UTT 64
#define D     1024
#define NM    (N_SPK * N_UTT)   // 32768
#define EPS   1e-6f
#define FP8_SCALE 16.0f          // embeddings scaled by 16 -> dot = 256*cos
#define INV_DOT_SCALE 0.00390625f // 1/256

// ---------------- scratch (device globals; no runtime allocation) ----------
__device__ uint8_t        g_cnorm[N_SPK * D];        // e4m3 centroids *16 (512 KiB)
__device__ uint8_t        g_enorm[(size_t)NM * D];   // e4m3 utterances *16 (32 MiB)
__device__ float          g_cos_self[NM];
__device__ float          g_prow[(size_t)NM * 4];    // per-row partial sum(exp) per N-slab
__device__ float          g_partial[128];
__device__ unsigned int   g_ctr = 0;                 // monotonic; %128 used per launch

// ---------------- helpers ---------------------------------------------------
__device__ __forceinline__ uint32_t smem_u32(const void* p) {
    uint32_t a;
    asm("{ .reg .u64 t; cvta.to.shared.u64 t, %1; cvt.u32.u64 %0, t; }" : "=r"(a) : "l"(p));
    return a;
}
__device__ __forceinline__ void cp_async16(uint32_t saddr, const void* gsrc) {
    asm volatile("cp.async.cg.shared.global [%0], [%1], 16;" :: "r"(saddr), "l"(gsrc) : "memory");
}
__device__ __forceinline__ void cp_commit() {
    asm volatile("cp.async.commit_group;" ::: "memory");
}
template <int N>
__device__ __forceinline__ void cp_wait() {
    asm volatile("cp.async.wait_group %0;" :: "n"(N) : "memory");
}
__device__ __forceinline__ void ldsm_x4(uint32_t& r0, uint32_t& r1, uint32_t& r2, uint32_t& r3,
                                        uint32_t addr) {
    asm volatile("ldmatrix.sync.aligned.m8n8.x4.shared.b16 {%0,%1,%2,%3}, [%4];"
                 : "=r"(r0), "=r"(r1), "=r"(r2), "=r"(r3) : "r"(addr));
}
// pack 4 floats -> 4 e4m3 bytes (little-endian order a,b,c,d)
__device__ __forceinline__ uint32_t pack_e4m3_4(float a, float b, float c, float d) {
    uint16_t lo, hi;
    asm("cvt.rn.satfinite.e4m3x2.f32 %0, %1, %2;" : "=h"(lo) : "f"(b), "f"(a));
    asm("cvt.rn.satfinite.e4m3x2.f32 %0, %1, %2;" : "=h"(hi) : "f"(d), "f"(c));
    return (uint32_t)lo | ((uint32_t)hi << 16);
}

__device__ __forceinline__ float warpReduceSum(float v) {
    #pragma unroll
    for (int o = 16; o > 0; o >>= 1) v += __shfl_xor_sync(0xFFFFFFFFu, v, o);
    return v;
}
__device__ __forceinline__ float blockReduceSumBcast(float v, float* sred) {
    int lane = threadIdx.x & 31, w = threadIdx.x >> 5;
    int nw = blockDim.x >> 5;
    v = warpReduceSum(v);
    if (lane == 0) sred[w] = v;
    __syncthreads();
    if (threadIdx.x < 32) {
        float x = (threadIdx.x < nw) ? sred[threadIdx.x] : 0.0f;
        x = warpReduceSum(x);
        if (threadIdx.x == 0) sred[0] = x;
    }
    __syncthreads();
    float r = sred[0];
    __syncthreads();
    return r;
}

// ---------------- kernel 1: per-speaker pre (warp-parallel pass 2) ---------
// Pass 1: block speaker sum -> smem S; centroid -> e4m3.
// Pass 2: warp w owns utterances m = w, w+8, ... Only xx and Sx dots needed:
//   uu = (SS - 2*Sx + xx)/63^2,  xu = (Sx - xx)/63.
__global__ void __launch_bounds__(256) pre_kernel(const float* __restrict__ inp) {
    __shared__ float Ssh[D];       // speaker sum vector (4 KiB)
    __shared__ float sred[32];
    const int n = blockIdx.x, t = threadIdx.x;
    const int lane = t & 31, w = t >> 5;
    const float4* base = reinterpret_cast<const float4*>(inp) + (size_t)n * N_UTT * (D / 4) + t;

    // ---- pass 1: speaker sum ----
    float4 s = make_float4(0.f, 0.f, 0.f, 0.f);
    #pragma unroll 8
    for (int m = 0; m < N_UTT; ++m) {
        float4 v = base[(size_t)m * (D / 4)];
        s.x += v.x; s.y += v.y; s.z += v.z; s.w += v.w;
    }
    reinterpret_cast<float4*>(Ssh)[t] = s;
    float ss = s.x * s.x + s.y * s.y + s.z * s.z + s.w * s.w;
    ss = blockReduceSumBcast(ss, sred);   // SS = |S|^2; barrier publishes Ssh
    const float SS = ss;
    {
        // centroid = S/64; |centroid|^2 = SS/4096
        const float invM = 1.0f / (float)N_UTT;
        float inv = FP8_SCALE * invM / sqrtf(fmaxf(SS * invM * invM, EPS));
        reinterpret_cast<uint32_t*>(g_cnorm)[(size_t)n * (D / 4) + t] =
            pack_e4m3_4(s.x * inv, s.y * inv, s.z * inv, s.w * inv);
    }

    // ---- pass 2: warp-parallel utterances, no block barriers ----
    const float invE = 1.0f / (float)(N_UTT - 1);
    const float4* Sv = reinterpret_cast<const float4*>(Ssh);
    for (int m = w; m < N_UTT; m += 8) {
        const float4* xrow = reinterpret_cast<const float4*>(inp)
                             + (size_t)(n * N_UTT + m) * (D / 4);
        float4 xs[8];
        float xx = 0.f, sx = 0.f;
        #pragma unroll
        for (int k = 0; k < 8; ++k) {
            float4 x = xrow[lane + 32 * k];
            float4 S = Sv[lane + 32 * k];
            xx += x.x * x.x + x.y * x.y + x.z * x.z + x.w * x.w;
            sx += S.x * x.x + S.y * x.y + S.z * x.z + S.w * x.w;
            xs[k] = x;
        }
        xx = warpReduceSum(xx);
        sx = warpReduceSum(sx);
        const float uu = (SS - 2.0f * sx + xx) * invE * invE;
        const float xu = (sx - xx) * invE;
        const float invx = 1.0f / sqrtf(fmaxf(xx, EPS));
        const float invu = 1.0f / sqrtf(fmaxf(uu, EPS));
        if (lane == 0) g_cos_self[n * N_UTT + m] = xu * invx * invu;
        const float sc = invx * FP8_SCALE;
        uint32_t* erow = reinterpret_cast<uint32_t*>(g_enorm) + (size_t)(n * N_UTT + m) * (D / 4);
        #pragma unroll
        for (int k = 0; k < 8; ++k) {
            erow[lane + 32 * k] = pack_e4m3_4(xs[k].x * sc, xs[k].y * sc,
                                              xs[k].z * sc, xs[k].w * sc);
        }
    }
}

// ---------------- kernel 2: fused FP8 GEMM + sum(exp) epilogue -------------
// Block tile 128x128, BK=64 e4m3 (64B rows), 3-stage cp.async, ldmatrix,
// mma.m16n8k32.e4m3, 2 CTAs/SM, single barrier per iteration.
#define TILE_B   8192                       // 128 rows x 64 bytes
#define STAGE_B  (2 * TILE_B)               // A + B = 16 KiB
__device__ __forceinline__ uint32_t swz(int row, int chunk) {
    return (uint32_t)(row * 64 + ((chunk ^ ((row >> 1) & 3)) << 4));
}

__global__ void __launch_bounds__(256, 2) gemm_fused(const float* __restrict__ wp,
                                                     const float* __restrict__ bp) {
    __shared__ __align__(16) char smem_raw[3 * STAGE_B];   // 48 KiB
    float* sred = reinterpret_cast<float*>(smem_raw);      // aliased in epilogue

    const int tid = threadIdx.x;
    const int bm = blockIdx.x, bn = blockIdx.y;
    const int warp = tid >> 5, lane = tid & 31;
    const int wm = warp & 1, wn = warp >> 1;     // 2 x 4 warp grid, warp tile 64x32
    const int g = lane >> 2, tg = lane & 3;
    const float W = *wp, Bb = *bp;
    const float Ws = W * INV_DOT_SCALE;          // acc = 256*cos
    const uint32_t sb = smem_u32(smem_raw);

    float acc[4][4][4];
    #pragma unroll
    for (int a = 0; a < 4; ++a)
        #pragma unroll
        for (int b = 0; b < 4; ++b)
            #pragma unroll
            for (int c = 0; c < 4; ++c) acc[a][b][c] = 0.f;

    const int r0 = tid >> 2, ch0 = tid & 3;
    const uint8_t* Ag = g_enorm + (size_t)(bm * 128 + r0) * D + ch0 * 16;
    const uint8_t* Bg = g_cnorm + (size_t)(bn * 128 + r0) * D + ch0 * 16;
    const uint32_t sa_lo = swz(r0, ch0), sa_hi = swz(r0 + 64, ch0);

    auto load_stage = [&](int stage, int kb) {
        const uint32_t base = sb + stage * STAGE_B;
        cp_async16(base + sa_lo,          Ag + kb);
        cp_async16(base + sa_hi,          Ag + (size_t)64 * D + kb);
        cp_async16(base + TILE_B + sa_lo, Bg + kb);
        cp_async16(base + TILE_B + sa_hi, Bg + (size_t)64 * D + kb);
    };

    const int a_row = wm * 64 + (lane & 15);                      // + mi*16
    const int a_ch  = lane >> 4;                                  // + kc
    const int b_row = wn * 32 + (lane & 7) + ((lane >> 4) << 3);  // + np*16
    const int b_ch  = (lane >> 3) & 1;                            // + kc

    // prologue
    load_stage(0, 0);  cp_commit();
    load_stage(1, 64); cp_commit();
    cp_wait<1>();
    __syncthreads();

    const int NKT = D / 64;  // 16
    for (int kt = 0; kt < NKT; ++kt) {
        const uint32_t abase = sb + (kt % 3) * STAGE_B;
        const uint32_t bbase = abase + TILE_B;
        #pragma unroll
        for (int kk = 0; kk < 2; ++kk) {       // two k32 halves of BK=64
            const int kc = kk * 2;             // 16B chunk index: 0 or 2
            uint32_t af[4][4];
            #pragma unroll
            for (int mi = 0; mi < 4; ++mi)
                ldsm_x4(af[mi][0], af[mi][1], af[mi][2], af[mi][3],
                        abase + swz(a_row + mi * 16, kc + a_ch));
            uint32_t bf_[4][2];
            #pragma unroll
            for (int np = 0; np < 2; ++np)
                ldsm_x4(bf_[2 * np][0], bf_[2 * np][1], bf_[2 * np + 1][0], bf_[2 * np + 1][1],
                        bbase + swz(b_row + np * 16, kc + b_ch));
            #pragma unroll
            for (int mi = 0; mi < 4; ++mi)
                #pragma unroll
                for (int ni = 0; ni < 4; ++ni) {
                    asm volatile(
                        "mma.sync.aligned.m16n8k32.row.col.f32.e4m3.e4m3.f32 "
                        "{%0,%1,%2,%3}, {%4,%5,%6,%7}, {%8,%9}, {%0,%1,%2,%3};\n"
                        : "+f"(acc[mi][ni][0]), "+f"(acc[mi][ni][1]),
                          "+f"(acc[mi][ni][2]), "+f"(acc[mi][ni][3])
                        : "r"(af[mi][0]), "r"(af[mi][1]), "r"(af[mi][2]), "r"(af[mi][3]),
                          "r"(bf_[ni][0]), "r"(bf_[ni][1]));
                }
        }
        if (kt + 2 < NKT) load_stage((kt + 2) % 3, (kt + 2) * 64);
        cp_commit();          // empty group when no loads -> uniform wait depth
        cp_wait<1>();         // stage kt+1 resident
        __syncthreads();      // one barrier per iteration
    }

    // ---- epilogue: per-row sum(exp(Ws*acc + B)), diag column excluded ----
    const int dcol_local = 2 * bm + wm - bn * 128;
    #pragma unroll
    for (int mi = 0; mi < 4; ++mi) {
        #pragma unroll
        for (int half = 0; half < 2; ++half) {
            float ex = 0.0f;
            #pragma unroll
            for (int ni = 0; ni < 4; ++ni) {
                const int c0 = wn * 32 + ni * 8 + 2 * tg;
                const float v0 = acc[mi][ni][half * 2 + 0];
                const float v1 = acc[mi][ni][half * 2 + 1];
                ex += (c0     == dcol_local) ? 0.0f : __expf(fmaf(Ws, v0, Bb));
                ex += (c0 + 1 == dcol_local) ? 0.0f : __expf(fmaf(Ws, v1, Bb));
            }
            ex += __shfl_xor_sync(0xFFFFFFFFu, ex, 1);
            ex += __shfl_xor_sync(0xFFFFFFFFu, ex, 2);
            if (tg == 0) {
                const int row_local = wm * 64 + mi * 16 + half * 8 + g;
                sred[row_local * 4 + wn] = ex;
            }
        }
    }
    __syncthreads();
    if (tid < 128) {
        const float* p = sred + tid * 4;
        const float S = (p[0] + p[1]) + (p[2] + p[3]);
        g_prow[(size_t)(bm * 128 + tid) * 4 + bn] = S;
    }
}

// ---------------- kernel 3: merge + threadfence final reduction ------------
// 128 blocks x 256 threads. Last-arriving block (atomic counter, replay-safe
// via %128) re-reduces the 128 partials in fixed order -> deterministic.
__global__ void __launch_bounds__(256) merge_kernel(const float* __restrict__ wp,
                                                    const float* __restrict__ bp,
                                                    float* __restrict__ out) {
    __shared__ float sred[32];
    __shared__ int slast;
    const int i = blockIdx.x * 256 + threadIdx.x;
    const float W = *wp, Bb = *bp;
    const float cs = g_cos_self[i];
    const float pos = fmaf(W, cs, Bb);
    const float4 p = *reinterpret_cast<const float4*>(g_prow + (size_t)i * 4);
    const float S = ((p.x + p.y) + (p.z + p.w)) + __expf(pos);
    float loss = __logf(S) - pos;
    loss = blockReduceSumBcast(loss, sred);
    if (threadIdx.x == 0) {
        g_partial[blockIdx.x] = loss;
        __threadfence();
        unsigned int old = atomicAdd(&g_ctr, 1u);
        slast = ((old & 127u) == 127u) ? 1 : 0;
    }
    __syncthreads();
    if (slast) {
        float v = (threadIdx.x < 128) ? g_partial[threadIdx.x] : 0.0f;
        v = blockReduceSumBcast(v, sred);
        if (threadIdx.x == 0) out[0] = v;
    }
}

// ---------------- launch ----------------------------------------------------
extern "C" void kernel_launch(void* const* d_in, const int* in_sizes, int n_in,
                              void* d_out, int out_size) {
    const float* inp = (const float*)d_in[0];
    const float* w   = (const float*)d_in[1];
    const float* b   = (const float*)d_in[2];
    float* out = (float*)d_out;

    pre_kernel<<<N_SPK, 256>>>(inp);
    dim3 gg(NM / 128, N_SPK / 128);
    gemm_fused<<<gg, 256>>>(w, b);
    merge_kernel<<<NM / 256, 256>>>(w, b, out);
}